// round 1
// baseline (speedup 1.0000x reference)
#include <cuda_runtime.h>
#include <cuda_bf16.h>

// Problem constants (fixed by setup_inputs): B=8, C=64, H=W=128, G=2, D=32, K=9, OS=2.0
#define PB 16384            // pixels per batch (H*W)
#define NB 8                // batch
#define NROWS (NB * PB)     // 131072 total "sequence rows"

// Scratch (static __device__ arrays — no allocation)
__device__ float g_value[NB * PB * 64];   // value projection output, (b,p,64)
__device__ float g_om[NB * PB * 54];      // offset/mask head output, (b,p,54)

// ---------------------------------------------------------------------------
// K1: value projection  val[p,j] = sum_c x[p,c] * vp_w[j,c] + vp_b[j]
// Block: 64 rows x 64 cols, 256 threads, 4x4 micro-tile per thread.
// ---------------------------------------------------------------------------
__global__ void __launch_bounds__(256) k1_valproj(const float* __restrict__ x,
                                                  const float* __restrict__ vp_w,
                                                  const float* __restrict__ vp_b) {
    __shared__ float Wt[64][68];   // Wt[c][j] = vp_w[j*64+c]  (padded, float4-readable)
    __shared__ float As[64][64];   // A tile [row][c]
    int t = threadIdx.x;
    for (int i = t; i < 4096; i += 256) Wt[i & 63][i >> 6] = vp_w[i];

    size_t row0 = (size_t)blockIdx.x * 64;
    const float4* xv = (const float4*)(x + row0 * 64);
    float4* asv = (float4*)&As[0][0];
    for (int i = t; i < 1024; i += 256) asv[i] = xv[i];
    __syncthreads();

    int j0 = (t & 15) * 4;
    int r0 = (t >> 4) * 4;
    float acc[4][4] = {};
#pragma unroll 8
    for (int c = 0; c < 64; c++) {
        float4 bv = *(const float4*)&Wt[c][j0];
#pragma unroll
        for (int i = 0; i < 4; i++) {
            float a = As[r0 + i][c];
            acc[i][0] = fmaf(a, bv.x, acc[i][0]);
            acc[i][1] = fmaf(a, bv.y, acc[i][1]);
            acc[i][2] = fmaf(a, bv.z, acc[i][2]);
            acc[i][3] = fmaf(a, bv.w, acc[i][3]);
        }
    }
    float4 bias = *(const float4*)(vp_b + j0);
#pragma unroll
    for (int i = 0; i < 4; i++) {
        float4 v = make_float4(acc[i][0] + bias.x, acc[i][1] + bias.y,
                               acc[i][2] + bias.z, acc[i][3] + bias.w);
        *(float4*)&g_value[(row0 + r0 + i) * 64 + j0] = v;
    }
}

// ---------------------------------------------------------------------------
// K2: depthwise 3x3 conv on xi (xi[b,c,h,w] = x[b, (h*W+w)*64 + c]) + bias,
//     then om GEMM (64 -> 54) + bias. One block = 64 consecutive pixels of a row.
// ---------------------------------------------------------------------------
__global__ void __launch_bounds__(256) k2_dwom(const float* __restrict__ x,
                                               const float* __restrict__ dw_w,
                                               const float* __restrict__ dw_b,
                                               const float* __restrict__ om_w,
                                               const float* __restrict__ om_b) {
    __shared__ float Wt[64][56];     // Wt[c][j] = om_w[j*64+c], j<54 (cols 54,55 zeroed)
    __shared__ float dws[64][65];    // dw[pixel][c], padded for conflict-free col reads
    __shared__ float ob[56];
    int t = threadIdx.x;
    for (int i = t; i < 54 * 64; i += 256) Wt[i & 63][i >> 6] = om_w[i];
    if (t < 128) Wt[t >> 1][54 + (t & 1)] = 0.f;
    if (t < 54) ob[t] = om_b[t];
    else if (t < 56) ob[t] = 0.f;

    int bb = blockIdx.x >> 8;             // batch
    int p0 = (blockIdx.x & 255) * 64;     // pixel tile start within batch
    int h = p0 >> 7;
    int w0 = p0 & 127;
    const float* xb = x + (size_t)bb * (PB * 64);

    // Phase A: depthwise conv. thread = (channel c, pixel group pg)
    int c = t & 63;
    int pg = t >> 6;
    float wk[9];
#pragma unroll
    for (int k = 0; k < 9; k++) wk[k] = dw_w[c * 9 + k];
    float bias = dw_b[c];
    for (int i = 0; i < 16; i++) {
        int pl = pg * 16 + i;
        int w = w0 + pl;
        float acc = bias;
#pragma unroll
        for (int ky = 0; ky < 3; ky++) {
            int yy = h + ky - 1;
            if ((unsigned)yy < 128u) {
#pragma unroll
                for (int kx = 0; kx < 3; kx++) {
                    int xx = w + kx - 1;
                    if ((unsigned)xx < 128u)
                        acc = fmaf(__ldg(xb + ((size_t)((yy << 7) + xx) << 6) + c),
                                   wk[ky * 3 + kx], acc);
                }
            }
        }
        dws[pl][c] = acc;
    }
    __syncthreads();

    // Phase B: om = dw @ om_w.T   (64 px x 54 out, k=64); thread = 4 px x 4 j
    int j0 = (t & 15) * 4;
    int px0 = (t >> 4) * 4;
    if (j0 < 54) {
        float acc2[4][4] = {};
#pragma unroll 8
        for (int cc = 0; cc < 64; cc++) {
            float4 bv = *(const float4*)&Wt[cc][j0];
#pragma unroll
            for (int i = 0; i < 4; i++) {
                float a = dws[px0 + i][cc];
                acc2[i][0] = fmaf(a, bv.x, acc2[i][0]);
                acc2[i][1] = fmaf(a, bv.y, acc2[i][1]);
                acc2[i][2] = fmaf(a, bv.z, acc2[i][2]);
                acc2[i][3] = fmaf(a, bv.w, acc2[i][3]);
            }
        }
        size_t base = ((size_t)bb * PB + p0 + px0) * 54;
#pragma unroll
        for (int i = 0; i < 4; i++) {
#pragma unroll
            for (int jj = 0; jj < 4; jj++) {
                int j = j0 + jj;
                if (j < 54) g_om[base + (size_t)i * 54 + j] = acc2[i][jj] + ob[j];
            }
        }
    }
}

// ---------------------------------------------------------------------------
// K3: DCN bilinear sampling + op GEMM + pairwise channel-fold + BN + ReLU.
// Block handles 16 pixel PAIRS: pixels [p0, p0+16) and [p0+8192, p0+8192+16)
// (these are the rows that fold together in the final reshape), so the output
// can be written directly with no out2 scratch.
// ---------------------------------------------------------------------------
__global__ void __launch_bounds__(256) k3_dcn(const float* __restrict__ op_w,
                                              const float* __restrict__ op_b,
                                              const float* __restrict__ bn_g,
                                              const float* __restrict__ bn_b,
                                              const float* __restrict__ bn_m,
                                              const float* __restrict__ bn_v,
                                              float* __restrict__ out) {
    __shared__ float Wop[64][68];   // Wop[c][j] = op_w[j*64+c]
    __shared__ float oms[32][54];   // staged offset/mask per local pixel
    __shared__ float cs[32][68];    // DCN core output per local pixel (64 ch)
    __shared__ float o2s[32][68];   // op-GEMM output per local pixel
    __shared__ float bnA[32], bnB[32], opb[64];
    int t = threadIdx.x;
    for (int i = t; i < 4096; i += 256) Wop[i & 63][i >> 6] = op_w[i];
    if (t < 64) opb[t] = op_b[t];
    if (t < 32) {
        float s = bn_g[t] * rsqrtf(bn_v[t] + 1e-5f);
        bnA[t] = s;
        bnB[t] = fmaf(-s, bn_m[t], bn_b[t]);
    }

    int bb = blockIdx.x >> 9;              // batch
    int p0 = (blockIdx.x & 511) * 16;      // pair-tile start, p0 in [0,8192)

    // Stage om for the 32 local pixels
    for (int i = t; i < 32 * 54; i += 256) {
        int pl = i / 54;
        int j = i - pl * 54;
        int pg = p0 + ((pl < 16) ? pl : (pl - 16 + 8192));
        oms[pl][j] = g_om[((size_t)bb * PB + pg) * 54 + j];
    }
    __syncthreads();

    // DCN: 16 lanes per pixel (4 channels each via one float4 gather per corner),
    // two passes to cover 32 local pixels with 256 threads.
    {
        int sub = t & 15;
        int g = sub >> 3;
        int d0 = (sub & 7) * 4;
        int plh = t >> 4;                  // 0..15
        const float* vb = g_value + (size_t)bb * (PB * 64) + g * 32 + d0;
#pragma unroll
        for (int pass = 0; pass < 2; pass++) {
            int pl = plh + pass * 16;
            int pg = p0 + plh + pass * 8192;
            int h = pg >> 7;
            int w = pg & 127;
            const float* omp = &oms[pl][g * 27];
            float a0 = 0.f, a1 = 0.f, a2 = 0.f, a3 = 0.f;
#pragma unroll
            for (int k = 0; k < 9; k++) {
                float ox = omp[2 * k], oy = omp[2 * k + 1], m = omp[18 + k];
                float ix = (float)w + ((float)(k % 3) - 1.0f + ox) * 2.0f;
                float iy = (float)h + ((float)(k / 3) - 1.0f + oy) * 2.0f;
                float xf = floorf(ix), yf = floorf(iy);
                float tx = ix - xf, ty = iy - yf;
                int x0 = (int)xf, y0 = (int)yf;
                float wx0 = 1.f - tx, wy0 = 1.f - ty;
#pragma unroll
                for (int cr = 0; cr < 4; cr++) {
                    int dy = cr >> 1, dx = cr & 1;
                    int xc = x0 + dx, yc = y0 + dy;
                    if ((unsigned)xc < 128u && (unsigned)yc < 128u) {
                        float wgt = (dy ? ty : wy0) * (dx ? tx : wx0) * m;
                        float4 v = __ldg((const float4*)(vb + ((size_t)((yc << 7) + xc) << 6)));
                        a0 = fmaf(wgt, v.x, a0);
                        a1 = fmaf(wgt, v.y, a1);
                        a2 = fmaf(wgt, v.z, a2);
                        a3 = fmaf(wgt, v.w, a3);
                    }
                }
            }
            *(float4*)&cs[pl][g * 32 + d0] = make_float4(a0, a1, a2, a3);
        }
    }
    __syncthreads();

    // op GEMM: out2[p,j] = sum_c core[p,c] * op_w[j,c] + op_b[j]
    // thread = 2 px x 4 j
    {
        int px0 = (t >> 4) * 2;
        int j0 = (t & 15) * 4;
        float o00 = 0.f, o01 = 0.f, o02 = 0.f, o03 = 0.f;
        float o10 = 0.f, o11 = 0.f, o12 = 0.f, o13 = 0.f;
#pragma unroll 8
        for (int c = 0; c < 64; c++) {
            float a0 = cs[px0][c];
            float a1 = cs[px0 + 1][c];
            float4 bv = *(const float4*)&Wop[c][j0];
            o00 = fmaf(a0, bv.x, o00); o01 = fmaf(a0, bv.y, o01);
            o02 = fmaf(a0, bv.z, o02); o03 = fmaf(a0, bv.w, o03);
            o10 = fmaf(a1, bv.x, o10); o11 = fmaf(a1, bv.y, o11);
            o12 = fmaf(a1, bv.z, o12); o13 = fmaf(a1, bv.w, o13);
        }
        float4 b4 = *(const float4*)&opb[j0];
        *(float4*)&o2s[px0][j0]     = make_float4(o00 + b4.x, o01 + b4.y, o02 + b4.z, o03 + b4.w);
        *(float4*)&o2s[px0 + 1][j0] = make_float4(o10 + b4.x, o11 + b4.y, o12 + b4.z, o13 + b4.w);
    }
    __syncthreads();

    // Epilogue: fold out2 pair rows (p, p+8192) -> z channel cz, BN, ReLU, store.
    // For p in [0,8192): flat f = p*64+j maps to (c = p>>8, h = (p&255)>>1, w = (p&1)*64+j)
    for (int oo = t; oo < 1024; oo += 256) {
        int i = oo >> 6;
        int j = oo & 63;
        int pA = p0 + i;
        float z = 0.5f * (o2s[i][j] + o2s[i + 16][j]);
        int cz = pA >> 8;
        int hh = (pA >> 1) & 127;
        int q = pA & 1;
        float r = fmaf(z, bnA[cz], bnB[cz]);
        out[(((size_t)bb * 32 + cz) * 128 + hh) * 128 + (q << 6) + j] = fmaxf(r, 0.f);
    }
}

// ---------------------------------------------------------------------------
extern "C" void kernel_launch(void* const* d_in, const int* in_sizes, int n_in,
                              void* d_out, int out_size) {
    const float* x    = (const float*)d_in[0];
    const float* vp_w = (const float*)d_in[1];
    const float* vp_b = (const float*)d_in[2];
    const float* dw_w = (const float*)d_in[3];
    const float* dw_b = (const float*)d_in[4];
    const float* om_w = (const float*)d_in[5];
    const float* om_b = (const float*)d_in[6];
    const float* op_w = (const float*)d_in[7];
    const float* op_b = (const float*)d_in[8];
    const float* bn_g = (const float*)d_in[9];
    const float* bn_b = (const float*)d_in[10];
    const float* bn_m = (const float*)d_in[11];
    const float* bn_v = (const float*)d_in[12];
    float* out = (float*)d_out;

    k1_valproj<<<NROWS / 64, 256>>>(x, vp_w, vp_b);
    k2_dwom<<<NB * (PB / 64), 256>>>(x, dw_w, dw_b, om_w, om_b);
    k3_dcn<<<NB * 512, 256>>>(op_w, op_b, bn_g, bn_b, bn_m, bn_v, out);
}